// round 9
// baseline (speedup 1.0000x reference)
#include <cuda_runtime.h>
#include <cuda_fp16.h>
#include <cstdint>

// ChebConv, commuted:
//   Agg[row, f] = sum_{e: rows[e]=row} vals[e] * x_flat[512*cols[e] + f]   (f in [0,512))
//   out[row*1536 + j*192 + q] = sum_k Agg[row, j*64+k] * w[k*192+q] + bias[q&63]
// Gather runs on an fp16 copy of x; accumulation fp32.
#define N_VERTEX 2048
#define NNZ_MAX  98304
#define ROW_LEN  1536
#define KCOLS    192
#define NSUB     4
#define SUB_CAP  48
#define SLOTS    (NSUB * SUB_CAP)    // 192, already a multiple of 16
#define TP       12
#define X_ELEMS  3145728
#define SCAT_BLK 384

__device__ int    g_cnt[N_VERTEX * NSUB];
__device__ float2 g_edge[N_VERTEX * NSUB * SUB_CAP];
__device__ __align__(16) __half g_xh[X_ELEMS];

typedef unsigned long long u64;
__device__ __forceinline__ u64 pk2(float a, float b) {
    u64 r; asm("mov.b64 %0, {%1, %2};" : "=l"(r) : "f"(a), "f"(b)); return r;
}
__device__ __forceinline__ u64 fma2(u64 a, u64 b, u64 c) {
    u64 d; asm("fma.rn.f32x2 %0, %1, %2, %3;" : "=l"(d) : "l"(a), "l"(b), "l"(c)); return d;
}
__device__ __forceinline__ u64 add2(u64 a, u64 b) {
    u64 d; asm("add.rn.f32x2 %0, %1, %2;" : "=l"(d) : "l"(a), "l"(b)); return d;
}
__device__ __forceinline__ uint4 ldg_nc_na(const void* p) {
    uint4 v;
    asm("ld.global.nc.L1::no_allocate.v4.u32 {%0,%1,%2,%3}, [%4];"
        : "=r"(v.x), "=r"(v.y), "=r"(v.z), "=r"(v.w) : "l"(p));
    return v;
}

// Fused prepass: blocks [0,SCAT_BLK) bucket-scatter edges; the rest convert x->fp16.
__global__ void k_prep(const float* __restrict__ x,
                       const float* __restrict__ vals,
                       const int*   __restrict__ rows,
                       const int*   __restrict__ cols, int nnz) {
    if (blockIdx.x < SCAT_BLK) {
        int i = blockIdx.x * blockDim.x + threadIdx.x;
        if (i < nnz) {
            int r   = rows[i];
            int sub = i & (NSUB - 1);
            int p   = atomicAdd(&g_cnt[r * NSUB + sub], 1);
            if (p < SUB_CAP)
                g_edge[(r * NSUB + sub) * SUB_CAP + p] =
                    make_float2(vals[i], __int_as_float(cols[i] * 1024));
        }
    } else {
        int i = (blockIdx.x - SCAT_BLK) * blockDim.x + threadIdx.x;
        if (i < X_ELEMS / 8) {
            float4 v0 = reinterpret_cast<const float4*>(x)[2 * i];
            float4 v1 = reinterpret_cast<const float4*>(x)[2 * i + 1];
            __half2 h0 = __floats2half2_rn(v0.x, v0.y);
            __half2 h1 = __floats2half2_rn(v0.z, v0.w);
            __half2 h2 = __floats2half2_rn(v1.x, v1.y);
            __half2 h3 = __floats2half2_rn(v1.z, v1.w);
            uint4 p;
            p.x = *reinterpret_cast<unsigned*>(&h0);
            p.y = *reinterpret_cast<unsigned*>(&h1);
            p.z = *reinterpret_cast<unsigned*>(&h2);
            p.w = *reinterpret_cast<unsigned*>(&h3);
            reinterpret_cast<uint4*>(g_xh)[i] = p;
        }
    }
}

#define ACC8(v, d)                                                              \
    do {                                                                        \
        float2 f0 = __half22float2(*reinterpret_cast<__half2*>(&(d).x));        \
        float2 f1 = __half22float2(*reinterpret_cast<__half2*>(&(d).y));        \
        float2 f2 = __half22float2(*reinterpret_cast<__half2*>(&(d).z));        \
        float2 f3 = __half22float2(*reinterpret_cast<__half2*>(&(d).w));        \
        a0 = fmaf((v), f0.x, a0); a1 = fmaf((v), f0.y, a1);                     \
        a2 = fmaf((v), f1.x, a2); a3 = fmaf((v), f1.y, a3);                     \
        a4 = fmaf((v), f2.x, a4); a5 = fmaf((v), f2.y, a5);                     \
        a6 = fmaf((v), f3.x, a6); a7 = fmaf((v), f3.y, a7);                     \
    } while (0)

// Fused per-row kernel: fp16 gather-aggregate -> transposed smem -> f32x2 GEMM.
// launch_bounds(256,4): 64-reg budget so the 4-deep gather pipeline stays in flight.
__global__ __launch_bounds__(256, 4) void k_main(
    const float* __restrict__ w,
    const float* __restrict__ bias,
    float* __restrict__ out)
{
    __shared__ alignas(16) float sP[4][512];
    __shared__ alignas(16) float sT[64 * TP];
    __shared__ float2 sE[SLOTS];
    __shared__ int    sCnt[NSUB];

    const int row = blockIdx.x;
    const int tid = threadIdx.x;

    if (tid < NSUB) {
        int c = g_cnt[row * NSUB + tid];
        sCnt[tid] = (c > SUB_CAP) ? SUB_CAP : c;
        g_cnt[row * NSUB + tid] = 0;
    }
    __syncthreads();
    const int c0 = sCnt[0], c1 = sCnt[1], c2 = sCnt[2], c3 = sCnt[3];
    const int deg    = c0 + c1 + c2 + c3;          // <= 192
    const int padded = (deg + 15) & ~15;           // pad to multiple of 16

    if (tid < padded) {
        if (tid < deg) {
            int b, pos;
            if      (tid < c0)           { b = 0; pos = tid; }
            else if (tid < c0 + c1)      { b = 1; pos = tid - c0; }
            else if (tid < c0 + c1 + c2) { b = 2; pos = tid - c0 - c1; }
            else                         { b = 3; pos = tid - c0 - c1 - c2; }
            sE[tid] = g_edge[(row * NSUB + b) * SUB_CAP + pos];
        } else {
            sE[tid] = make_float2(0.f, __int_as_float(0));   // zero-edge: val 0
        }
    }
    __syncthreads();

    // ---- Phase 1: 4-deep software-pipelined fp16 gather ----
    {
        const int lane = tid & 63;                 // owns halfs 8*lane .. 8*lane+7
        const int grp  = tid >> 6;                 // 4 edge-groups
        float a0=0.f,a1=0.f,a2=0.f,a3=0.f,a4=0.f,a5=0.f,a6=0.f,a7=0.f;
        const char* xb = (const char*)g_xh + lane * 16;
        const int nIt = padded >> 4;               // 4 edges per group per iter
        for (int it = 0; it < nIt; ++it) {
            const int base = grp + (it << 4);
            float2 e0 = sE[base];
            float2 e1 = sE[base + 4];
            float2 e2 = sE[base + 8];
            float2 e3 = sE[base + 12];
            uint4 d0 = ldg_nc_na(xb + __float_as_int(e0.y));
            uint4 d1 = ldg_nc_na(xb + __float_as_int(e1.y));
            uint4 d2 = ldg_nc_na(xb + __float_as_int(e2.y));
            uint4 d3 = ldg_nc_na(xb + __float_as_int(e3.y));
            ACC8(e0.x, d0);
            ACC8(e1.x, d1);
            ACC8(e2.x, d2);
            ACC8(e3.x, d3);
        }
        float* sp = &sP[grp][8 * lane];
        *(float4*)(sp)     = make_float4(a0, a1, a2, a3);
        *(float4*)(sp + 4) = make_float4(a4, a5, a6, a7);
    }
    __syncthreads();

    // merge 4 partials + transpose into sT
    if (tid < 128) {
        const int f = 4 * tid;
        float4 p0 = *(const float4*)&sP[0][f];
        float4 p1 = *(const float4*)&sP[1][f];
        float4 p2 = *(const float4*)&sP[2][f];
        float4 p3 = *(const float4*)&sP[3][f];
        const int j  = f >> 6;
        const int k0 = f & 63;
        sT[TP * k0 + j]       = (p0.x + p1.x) + (p2.x + p3.x);
        sT[TP * (k0 + 1) + j] = (p0.y + p1.y) + (p2.y + p3.y);
        sT[TP * (k0 + 2) + j] = (p0.z + p1.z) + (p2.z + p3.z);
        sT[TP * (k0 + 3) + j] = (p0.w + p1.w) + (p2.w + p3.w);
    }
    __syncthreads();

    // ---- Phase 2: [8,64]@[64,192] + bias; j-paired f32x2 ----
    if (tid < KCOLS) {
        const int q = tid;
        u64 acc0 = 0ull, acc1 = 0ull, acc2 = 0ull, acc3 = 0ull;
        const float* wq = w + q;
        #pragma unroll 8
        for (int k = 0; k < 64; ++k) {
            float wv = __ldg(wq + k * KCOLS);
            u64 wd = pk2(wv, wv);
            ulonglong2 b0 = *(const ulonglong2*)(sT + TP * k);
            ulonglong2 b1 = *(const ulonglong2*)(sT + TP * k + 4);
            acc0 = fma2(b0.x, wd, acc0);
            acc1 = fma2(b0.y, wd, acc1);
            acc2 = fma2(b1.x, wd, acc2);
            acc3 = fma2(b1.y, wd, acc3);
        }
        const float bv = __ldg(&bias[q & 63]);
        const u64 bd = pk2(bv, bv);
        acc0 = add2(acc0, bd); acc1 = add2(acc1, bd);
        acc2 = add2(acc2, bd); acc3 = add2(acc3, bd);
        float* op = out + (size_t)row * ROW_LEN + q;
        u64 accs[4] = {acc0, acc1, acc2, acc3};
        #pragma unroll
        for (int p = 0; p < 4; ++p) {
            float lo, hi;
            asm("mov.b64 {%0, %1}, %2;" : "=f"(lo), "=f"(hi) : "l"(accs[p]));
            op[(2 * p)     * KCOLS] = lo;
            op[(2 * p + 1) * KCOLS] = hi;
        }
    }
}

extern "C" void kernel_launch(void* const* d_in, const int* in_sizes, int n_in,
                              void* d_out, int out_size) {
    const float* x    = (const float*)d_in[0];
    const float* w    = (const float*)d_in[1];
    const float* bias = (const float*)d_in[2];
    const float* fv   = (const float*)d_in[3];
    const int*   fr   = (const int*)d_in[4];
    const int*   fc   = (const int*)d_in[5];
    int nnz = in_sizes[3];
    if (nnz > NNZ_MAX) nnz = NNZ_MAX;
    float* out = (float*)d_out;

    const int conv_blocks = (X_ELEMS / 8 + 255) / 256;   // 1536
    k_prep<<<SCAT_BLK + conv_blocks, 256>>>(x, fv, fr, fc, nnz);
    k_main<<<N_VERTEX, 256>>>(w, bias, out);
}

// round 10
// speedup vs baseline: 1.2043x; 1.2043x over previous
#include <cuda_runtime.h>
#include <cuda_fp16.h>
#include <cstdint>

// ChebConv, commuted:
//   Agg[row, f] = sum_{e: rows[e]=row} vals[e] * x_flat[512*cols[e] + f]   (f in [0,512))
//   out[row*1536 + j*192 + q] = sum_k Agg[row, j*64+k] * w[k*192+q] + bias[q&63]
// fp16 gather (halved L2 traffic), fp32 accumulation. 2 rows per block.
#define N_VERTEX 2048
#define NNZ_MAX  98304
#define ROW_LEN  1536
#define KCOLS    192
#define NSUB     4
#define SUB_CAP  48
#define SLOTS    (NSUB * SUB_CAP)
#define TP       12
#define X_ELEMS  3145728
#define SCAT_BLK 384

__device__ int    g_cnt[N_VERTEX * NSUB];
__device__ float2 g_edge[N_VERTEX * NSUB * SUB_CAP];
__device__ __align__(16) __half g_xh[X_ELEMS];

typedef unsigned long long u64;
__device__ __forceinline__ u64 pk2(float a, float b) {
    u64 r; asm("mov.b64 %0, {%1, %2};" : "=l"(r) : "f"(a), "f"(b)); return r;
}
__device__ __forceinline__ u64 fma2(u64 a, u64 b, u64 c) {
    u64 d; asm("fma.rn.f32x2 %0, %1, %2, %3;" : "=l"(d) : "l"(a), "l"(b), "l"(c)); return d;
}
__device__ __forceinline__ u64 add2(u64 a, u64 b) {
    u64 d; asm("add.rn.f32x2 %0, %1, %2;" : "=l"(d) : "l"(a), "l"(b)); return d;
}
__device__ __forceinline__ uint4 ldg_nc_na(const void* p) {
    uint4 v;
    asm("ld.global.nc.L1::no_allocate.v4.u32 {%0,%1,%2,%3}, [%4];"
        : "=r"(v.x), "=r"(v.y), "=r"(v.z), "=r"(v.w) : "l"(p));
    return v;
}

// Fused prepass: blocks [0,SCAT_BLK) bucket-scatter edges; the rest convert x->fp16.
__global__ void k_prep(const float* __restrict__ x,
                       const float* __restrict__ vals,
                       const int*   __restrict__ rows,
                       const int*   __restrict__ cols, int nnz) {
    if (blockIdx.x < SCAT_BLK) {
        int i = blockIdx.x * blockDim.x + threadIdx.x;
        if (i < nnz) {
            int r   = rows[i];
            int sub = i & (NSUB - 1);
            int p   = atomicAdd(&g_cnt[r * NSUB + sub], 1);
            if (p < SUB_CAP)
                g_edge[(r * NSUB + sub) * SUB_CAP + p] =
                    make_float2(vals[i], __int_as_float(cols[i] * 1024));
        }
    } else {
        int i = (blockIdx.x - SCAT_BLK) * blockDim.x + threadIdx.x;
        if (i < X_ELEMS / 8) {
            float4 v0 = reinterpret_cast<const float4*>(x)[2 * i];
            float4 v1 = reinterpret_cast<const float4*>(x)[2 * i + 1];
            __half2 h0 = __floats2half2_rn(v0.x, v0.y);
            __half2 h1 = __floats2half2_rn(v0.z, v0.w);
            __half2 h2 = __floats2half2_rn(v1.x, v1.y);
            __half2 h3 = __floats2half2_rn(v1.z, v1.w);
            uint4 p;
            p.x = *reinterpret_cast<unsigned*>(&h0);
            p.y = *reinterpret_cast<unsigned*>(&h1);
            p.z = *reinterpret_cast<unsigned*>(&h2);
            p.w = *reinterpret_cast<unsigned*>(&h3);
            reinterpret_cast<uint4*>(g_xh)[i] = p;
        }
    }
}

// 2 rows per block: fp16 gather -> transposed smem -> f32x2 GEMM with shared w loads.
__global__ __launch_bounds__(256) void k_main(
    const float* __restrict__ w,
    const float* __restrict__ bias,
    float* __restrict__ out)
{
    __shared__ alignas(16) float  sP[4][512];      // partials: [0,1]=rowA, [2,3]=rowB
    __shared__ alignas(16) float  sTA[64 * TP];    // transposed Agg row A
    __shared__ alignas(16) float  sTB[64 * TP];    // transposed Agg row B
    __shared__ float2 sEA[SLOTS], sEB[SLOTS];
    __shared__ int    sCnt[2 * NSUB];

    const int rowA = 2 * blockIdx.x;
    const int rowB = rowA + 1;
    const int tid  = threadIdx.x;

    if (tid < 2 * NSUB) {
        int idx = rowA * NSUB + tid;               // covers both rows' counters
        int c = g_cnt[idx];
        sCnt[tid] = (c > SUB_CAP) ? SUB_CAP : c;
        g_cnt[idx] = 0;
    }
    __syncthreads();
    const int a0c = sCnt[0], a1c = sCnt[1], a2c = sCnt[2], a3c = sCnt[3];
    const int b0c = sCnt[4], b1c = sCnt[5], b2c = sCnt[6], b3c = sCnt[7];
    const int degA = a0c + a1c + a2c + a3c;        // <= 192
    const int degB = b0c + b1c + b2c + b3c;

    if (tid < degA) {
        int b, pos;
        if      (tid < a0c)             { b = 0; pos = tid; }
        else if (tid < a0c + a1c)       { b = 1; pos = tid - a0c; }
        else if (tid < a0c + a1c + a2c) { b = 2; pos = tid - a0c - a1c; }
        else                            { b = 3; pos = tid - a0c - a1c - a2c; }
        sEA[tid] = g_edge[(rowA * NSUB + b) * SUB_CAP + pos];
    }
    if (tid < degB) {
        int b, pos;
        if      (tid < b0c)             { b = 0; pos = tid; }
        else if (tid < b0c + b1c)       { b = 1; pos = tid - b0c; }
        else if (tid < b0c + b1c + b2c) { b = 2; pos = tid - b0c - b1c; }
        else                            { b = 3; pos = tid - b0c - b1c - b2c; }
        sEB[tid] = g_edge[(rowB * NSUB + b) * SUB_CAP + pos];
    }
    __syncthreads();

    // ---- Phase 1: fp16 gather; 64 lanes x 4 groups (2 per row, 2-way edge split) ----
    {
        const int lane = tid & 63;                 // owns halfs 8*lane .. 8*lane+7
        const int grp  = tid >> 6;                 // 0,1 -> rowA; 2,3 -> rowB
        const int sub  = grp & 1;
        const float2* eL = (grp < 2) ? sEA : sEB;
        const int     dg = (grp < 2) ? degA : degB;
        float a0=0.f,a1=0.f,a2=0.f,a3=0.f,a4=0.f,a5=0.f,a6=0.f,a7=0.f;
        const char* xb = (const char*)g_xh + lane * 16;
        #pragma unroll 12
        for (int i = sub; i < dg; i += 2) {
            float2 ed = eL[i];                                    // LDS.64 broadcast
            uint4 d = ldg_nc_na(xb + __float_as_int(ed.y));       // LDG.128, L1 no-alloc
            float v = ed.x;
            float2 f0 = __half22float2(*reinterpret_cast<__half2*>(&d.x));
            float2 f1 = __half22float2(*reinterpret_cast<__half2*>(&d.y));
            float2 f2 = __half22float2(*reinterpret_cast<__half2*>(&d.z));
            float2 f3 = __half22float2(*reinterpret_cast<__half2*>(&d.w));
            a0 = fmaf(v, f0.x, a0); a1 = fmaf(v, f0.y, a1);
            a2 = fmaf(v, f1.x, a2); a3 = fmaf(v, f1.y, a3);
            a4 = fmaf(v, f2.x, a4); a5 = fmaf(v, f2.y, a5);
            a6 = fmaf(v, f3.x, a6); a7 = fmaf(v, f3.y, a7);
        }
        float* sp = &sP[grp][8 * lane];
        *(float4*)(sp)     = make_float4(a0, a1, a2, a3);
        *(float4*)(sp + 4) = make_float4(a4, a5, a6, a7);
    }
    __syncthreads();

    // merge 2 partials per row + transpose (256 threads: low half rowA, high half rowB)
    {
        const int r = tid >> 7;                    // 0=rowA, 1=rowB
        const int t = tid & 127;
        const int f = 4 * t;
        float4 p0 = *(const float4*)&sP[2 * r][f];
        float4 p1 = *(const float4*)&sP[2 * r + 1][f];
        float* dst = r ? sTB : sTA;
        const int j  = f >> 6;
        const int k0 = f & 63;
        dst[TP * k0 + j]       = p0.x + p1.x;
        dst[TP * (k0 + 1) + j] = p0.y + p1.y;
        dst[TP * (k0 + 2) + j] = p0.z + p1.z;
        dst[TP * (k0 + 3) + j] = p0.w + p1.w;
    }
    __syncthreads();

    // ---- Phase 2: two [8,64]@[64,192] GEMMs sharing each w load ----
    if (tid < KCOLS) {
        const int q = tid;
        u64 A0=0ull,A1=0ull,A2=0ull,A3=0ull, B0=0ull,B1=0ull,B2=0ull,B3=0ull;
        const float* wq = w + q;
        #pragma unroll 8
        for (int k = 0; k < 64; ++k) {
            float wv = __ldg(wq + k * KCOLS);                    // 1 line/warp, L1-resident
            u64 wd = pk2(wv, wv);
            ulonglong2 xa0 = *(const ulonglong2*)(sTA + TP * k);
            ulonglong2 xa1 = *(const ulonglong2*)(sTA + TP * k + 4);
            ulonglong2 xb0 = *(const ulonglong2*)(sTB + TP * k);
            ulonglong2 xb1 = *(const ulonglong2*)(sTB + TP * k + 4);
            A0 = fma2(xa0.x, wd, A0);  A1 = fma2(xa0.y, wd, A1);
            A2 = fma2(xa1.x, wd, A2);  A3 = fma2(xa1.y, wd, A3);
            B0 = fma2(xb0.x, wd, B0);  B1 = fma2(xb0.y, wd, B1);
            B2 = fma2(xb1.x, wd, B2);  B3 = fma2(xb1.y, wd, B3);
        }
        const float bv = __ldg(&bias[q & 63]);
        const u64 bd = pk2(bv, bv);
        float* opA = out + (size_t)rowA * ROW_LEN + q;
        float* opB = out + (size_t)rowB * ROW_LEN + q;
        u64 accA[4] = {add2(A0,bd), add2(A1,bd), add2(A2,bd), add2(A3,bd)};
        u64 accB[4] = {add2(B0,bd), add2(B1,bd), add2(B2,bd), add2(B3,bd)};
        #pragma unroll
        for (int p = 0; p < 4; ++p) {
            float lo, hi;
            asm("mov.b64 {%0, %1}, %2;" : "=f"(lo), "=f"(hi) : "l"(accA[p]));
            opA[(2 * p) * KCOLS]     = lo;
            opA[(2 * p + 1) * KCOLS] = hi;
            asm("mov.b64 {%0, %1}, %2;" : "=f"(lo), "=f"(hi) : "l"(accB[p]));
            opB[(2 * p) * KCOLS]     = lo;
            opB[(2 * p + 1) * KCOLS] = hi;
        }
    }
}

extern "C" void kernel_launch(void* const* d_in, const int* in_sizes, int n_in,
                              void* d_out, int out_size) {
    const float* x    = (const float*)d_in[0];
    const float* w    = (const float*)d_in[1];
    const float* bias = (const float*)d_in[2];
    const float* fv   = (const float*)d_in[3];
    const int*   fr   = (const int*)d_in[4];
    const int*   fc   = (const int*)d_in[5];
    int nnz = in_sizes[3];
    if (nnz > NNZ_MAX) nnz = NNZ_MAX;
    float* out = (float*)d_out;

    const int conv_blocks = (X_ELEMS / 8 + 255) / 256;   // 1536
    k_prep<<<SCAT_BLK + conv_blocks, 256>>>(x, fv, fr, fc, nnz);
    k_main<<<N_VERTEX / 2, 256>>>(w, bias, out);
}